// round 12
// baseline (speedup 1.0000x reference)
#include <cuda_runtime.h>
#include <cuda_bf16.h>
#include <math_constants.h>
#include <cstdint>

#define N_NODES 50000
#define N_EDGES 800000
#define D 128
#define N_GRAPHS 64
#define SCAN_BLK 1024
#define N_SCAN_BLKS ((N_NODES + SCAN_BLK - 1) / SCAN_BLK)   // 49
#define POOL_CHUNKS 8

// GEMM smem layout in uint32 units, plain bf16 tiles (ldmatrix-friendly).
// W tile: 16 k-rows x 128 n bf16, row stride 68 u32 (272B = 17*16B: conflict-free)
// A tile: 64 m-rows x 16 k bf16, row stride 12 u32 (48B = 3*16B: conflict-free)
#define WSTRB 68
#define WBUFB (16 * WSTRB)       // 1088
#define ASTRB 12
#define ABUFB (64 * ASTRB)       // 768
#define S_WH 0
#define S_WL (2 * WBUFB)                   // 2176
#define S_AH (4 * WBUFB)                   // 4352
#define S_AL (4 * WBUFB + 2 * ABUFB)       // 5888
#define S_TOT (4 * WBUFB + 4 * ABUFB)      // 7424 u32 = 29696 B

// ------------------------- device scratch ----------------------------------
__device__ float    g_dis[N_NODES];
__device__ int      g_deg[N_NODES];         // zeroed by k_scan23 for next call
__device__ int      g_rowoff[N_NODES + 1];
__device__ int      g_next[N_NODES];
__device__ int      g_bsum[N_SCAN_BLKS];
__device__ int      g_col[N_EDGES];
__device__ float    g_h[N_NODES * D];       // dis-scaled x @ W
__device__ float    g_agg[N_NODES * D];
__device__ float    g_pmax[N_GRAPHS * POOL_CHUNKS * D];
__device__ uint32_t g_Wbh[3 * 128 * 64];    // plain bf16 hi, [layer][k][n] (2n/u32)
__device__ uint32_t g_Wbl[3 * 128 * 64];    // plain bf16 lo

// ------------------------- helpers -----------------------------------------
__device__ __forceinline__ void split_pack(float x, float y,
                                           uint32_t& hi, uint32_t& lo) {
    __nv_bfloat162 h2 = __floats2bfloat162_rn(x, y);
    float rx = x - __bfloat162float(h2.x);
    float ry = y - __bfloat162float(h2.y);
    __nv_bfloat162 l2 = __floats2bfloat162_rn(rx, ry);
    hi = *reinterpret_cast<uint32_t*>(&h2);
    lo = *reinterpret_cast<uint32_t*>(&l2);
}

#define MMA_BF16(C, A0, A1, A2, A3, B0, B1)                                   \
    asm volatile(                                                             \
        "mma.sync.aligned.m16n8k16.row.col.f32.bf16.bf16.f32 "                \
        "{%0,%1,%2,%3}, {%4,%5,%6,%7}, {%8,%9}, {%0,%1,%2,%3};"               \
        : "+f"(C[0]), "+f"(C[1]), "+f"(C[2]), "+f"(C[3])                      \
        : "r"(A0), "r"(A1), "r"(A2), "r"(A3), "r"(B0), "r"(B1))

__device__ __forceinline__ void ldsm_x4(uint32_t& r0, uint32_t& r1,
                                        uint32_t& r2, uint32_t& r3,
                                        uint32_t addr) {
    asm volatile("ldmatrix.sync.aligned.m8n8.x4.shared.b16 {%0,%1,%2,%3}, [%4];"
                 : "=r"(r0), "=r"(r1), "=r"(r2), "=r"(r3) : "r"(addr));
}
__device__ __forceinline__ void ldsm_x4_t(uint32_t& r0, uint32_t& r1,
                                          uint32_t& r2, uint32_t& r3,
                                          uint32_t addr) {
    asm volatile("ldmatrix.sync.aligned.m8n8.x4.trans.shared.b16 {%0,%1,%2,%3}, [%4];"
                 : "=r"(r0), "=r"(r1), "=r"(r2), "=r"(r3) : "r"(addr));
}

__device__ __forceinline__ void cp_async16u(uint32_t* dst_smem, const uint32_t* src) {
    unsigned d = (unsigned)__cvta_generic_to_shared(dst_smem);
    asm volatile("cp.async.cg.shared.global [%0], [%1], 16;" :: "r"(d), "l"(src));
}
__device__ __forceinline__ void cp_commit() {
    asm volatile("cp.async.commit_group;");
}
__device__ __forceinline__ void cp_wait0() {
    asm volatile("cp.async.wait_group 0;");
}

// ------------------------- CSR build ---------------------------------------
__global__ void k_count(const int* __restrict__ dst) {
    int i = blockIdx.x * blockDim.x + threadIdx.x;
    if (i < N_EDGES) atomicAdd(&g_deg[dst[i]], 1);
}

__global__ __launch_bounds__(SCAN_BLK) void k_scan1() {
    __shared__ int wsum[32];
    int t = threadIdx.x;
    int lane = t & 31, warp = t >> 5;
    int i = blockIdx.x * SCAN_BLK + t;
    int v = (i < N_NODES) ? g_deg[i] : 0;
    int incl = v;
#pragma unroll
    for (int off = 1; off < 32; off <<= 1) {
        int u = __shfl_up_sync(0xffffffffu, incl, off);
        if (lane >= off) incl += u;
    }
    if (lane == 31) wsum[warp] = incl;
    __syncthreads();
    if (warp == 0) {
        int w = wsum[lane];
        int wi = w;
#pragma unroll
        for (int off = 1; off < 32; off <<= 1) {
            int u = __shfl_up_sync(0xffffffffu, wi, off);
            if (lane >= off) wi += u;
        }
        wsum[lane] = wi - w;
    }
    __syncthreads();
    int inclTot = incl + wsum[warp];
    if (i < N_NODES) {
        g_rowoff[i] = inclTot - v;
        g_dis[i] = rsqrtf((float)v + 1.0f);
    }
    if (t == SCAN_BLK - 1) g_bsum[blockIdx.x] = inclTot;
}

__global__ __launch_bounds__(SCAN_BLK) void k_scan23() {
    __shared__ int s[64];
    int t = threadIdx.x;
    if (t < 64) {
        int v = (t < N_SCAN_BLKS) ? g_bsum[t] : 0;
        s[t] = v;
        __syncthreads();
#pragma unroll
        for (int off = 1; off < 64; off <<= 1) {
            int add = (t >= off) ? s[t - off] : 0;
            __syncthreads();
            s[t] += add;
            __syncthreads();
        }
        int v2 = (t < N_SCAN_BLKS) ? g_bsum[t] : 0;
        s[t] -= v2;
    } else {
        __syncthreads();
#pragma unroll
        for (int off = 1; off < 64; off <<= 1) { __syncthreads(); __syncthreads(); }
    }
    __syncthreads();
    int boff = s[blockIdx.x];
    int i = blockIdx.x * SCAN_BLK + t;
    if (i < N_NODES) {
        int fin = g_rowoff[i] + boff;
        g_rowoff[i] = fin;
        g_next[i] = fin;
        g_deg[i] = 0;
    }
    if (i == 0) g_rowoff[N_NODES] = N_EDGES;
}

__global__ void k_fill(const int* __restrict__ src, const int* __restrict__ dst) {
    int i = blockIdx.x * blockDim.x + threadIdx.x;
    if (i < N_EDGES) {
        int pos = atomicAdd(&g_next[dst[i]], 1);
        g_col[pos] = src[i];
    }
}

// ------------------------- weight pre-split (plain bf16 hi/lo) -------------
// g_Wb*[layer*8192 + k*64 + n2] = bf16x2{ W[k][2n2], W[k][2n2+1] }
__global__ void k_splitW(const float* __restrict__ W1,
                         const float* __restrict__ W2,
                         const float* __restrict__ W3) {
    int i = blockIdx.x * blockDim.x + threadIdx.x;     // 0..24575
    if (i >= 3 * 128 * 64) return;
    int m = i >> 13, r = i & 8191;
    int k = r >> 6, n2 = r & 63;
    const float* Ws = (m == 0) ? W1 : ((m == 1) ? W2 : W3);
    float x0 = Ws[k * D + 2 * n2];
    float x1 = Ws[k * D + 2 * n2 + 1];
    uint32_t hi, lo;
    split_pack(x0, x1, hi, lo);
    g_Wbh[i] = hi;
    g_Wbl[i] = lo;
}

// ------------------------- pipelined bf16x3 GEMM, M-tile 64 ----------------
// 256 threads (8 warps as 2x4: M=32,N=32 per warp), K chunk 16,
// double-buffered (cp.async W, register-staged A), 3 CTAs/SM target.
// MMA issue order: terms outermost within each n-pair group so dependent
// MMAs on one accumulator are separated by 3 independent ones.
__global__ __launch_bounds__(256, 3) void k_gemm_tc(const float* __restrict__ A,
                                                    const uint32_t* __restrict__ Wbh,
                                                    const uint32_t* __restrict__ Wbl,
                                                    float* __restrict__ Hout) {
    __shared__ uint32_t sm[S_TOT];
    int tid  = threadIdx.x;
    int warp = tid >> 5, lane = tid & 31;
    int g = lane >> 2, tg = lane & 3;
    int wm = warp & 1, wn = warp >> 1;          // 2x4 warp grid
    int row0 = blockIdx.x * 64;

    // copy coordinates: W chunk = 16 rows x 64 u32; one 16B cp per thread
    int wrr = tid >> 4, wcc = (tid & 15) * 4;
    // A staging: row ar (0..63); float col afc; u32 pair col apc
    int ar = tid >> 2;
    int afc = (tid & 3) * 4;
    int apc = (tid & 3) * 2;

    // ldmatrix lane addressing
    int rowsel = ((lane >> 3) & 1) * 8 + (lane & 7);
    int half4 = (lane >> 4) * 4;
    uint32_t smb = (uint32_t)__cvta_generic_to_shared(sm);
    uint32_t a_addr[2];
#pragma unroll
    for (int mt = 0; mt < 2; mt++)
        a_addr[mt] = smb + (uint32_t)(S_AH + (wm * 32 + mt * 16 + rowsel) * ASTRB + half4) * 4;
    uint32_t w_addr[2];
#pragma unroll
    for (int p = 0; p < 2; p++)
        w_addr[p] = smb + (uint32_t)(S_WH + rowsel * WSTRB + wn * 16 + p * 8 + half4) * 4;

    const uint32_t ALOFF = (uint32_t)(S_AL - S_AH) * 4;
    const uint32_t WLOFF = (uint32_t)(S_WL - S_WH) * 4;

    float acc[2][4][4];
#pragma unroll
    for (int mt = 0; mt < 2; mt++)
#pragma unroll
        for (int nt = 0; nt < 4; nt++)
#pragma unroll
            for (int c = 0; c < 4; c++) acc[mt][nt][c] = 0.0f;

    // ---- prologue: stage chunk 0 into buffer 0
    cp_async16u(&sm[S_WH + wrr * WSTRB + wcc], Wbh + wrr * 64 + wcc);
    cp_async16u(&sm[S_WL + wrr * WSTRB + wcc], Wbl + wrr * 64 + wcc);
    cp_commit();
    {
        int gr = row0 + ar;
        float4 v = make_float4(0.f, 0.f, 0.f, 0.f);
        if (gr < N_NODES) v = *(const float4*)(A + (size_t)gr * D + afc);
        uint32_t h0, l0, h1, l1;
        split_pack(v.x, v.y, h0, l0);
        split_pack(v.z, v.w, h1, l1);
        *(uint2*)&sm[S_AH + ar * ASTRB + apc] = make_uint2(h0, h1);
        *(uint2*)&sm[S_AL + ar * ASTRB + apc] = make_uint2(l0, l1);
    }
    cp_wait0();
    __syncthreads();

    for (int kc = 0; kc < 8; kc++) {
        int buf = kc & 1, nxt = buf ^ 1;
        bool pre = (kc < 7);
        float4 v0;
        if (pre) {
            const uint32_t* wh = Wbh + (kc + 1) * 1024;
            const uint32_t* wl = Wbl + (kc + 1) * 1024;
            cp_async16u(&sm[S_WH + nxt * WBUFB + wrr * WSTRB + wcc], wh + wrr * 64 + wcc);
            cp_async16u(&sm[S_WL + nxt * WBUFB + wrr * WSTRB + wcc], wl + wrr * 64 + wcc);
            cp_commit();
            int kcol = (kc + 1) * 16 + afc;
            v0 = make_float4(0.f, 0.f, 0.f, 0.f);
            int gr = row0 + ar;
            if (gr < N_NODES) v0 = *(const float4*)(A + (size_t)gr * D + kcol);
        }

        // ---- MMAs on current buffer (one k16 step)
        uint32_t abufo = (uint32_t)(buf * ABUFB) * 4;
        uint32_t wbufo = (uint32_t)(buf * WBUFB) * 4;

        uint32_t ah[2][4], al[2][4];
#pragma unroll
        for (int mt = 0; mt < 2; mt++) {
            ldsm_x4(ah[mt][0], ah[mt][1], ah[mt][2], ah[mt][3], a_addr[mt] + abufo);
            ldsm_x4(al[mt][0], al[mt][1], al[mt][2], al[mt][3], a_addr[mt] + abufo + ALOFF);
        }
#pragma unroll
        for (int p = 0; p < 2; p++) {
            uint32_t bh0, bh1, bh2, bh3, bl0, bl1, bl2, bl3;
            ldsm_x4_t(bh0, bh1, bh2, bh3, w_addr[p] + wbufo);
            ldsm_x4_t(bl0, bl1, bl2, bl3, w_addr[p] + wbufo + WLOFF);
            // term Ah*Bh — 4 independent accumulators
#pragma unroll
            for (int mt = 0; mt < 2; mt++) {
                MMA_BF16(acc[mt][2 * p],     ah[mt][0], ah[mt][1], ah[mt][2], ah[mt][3], bh0, bh1);
                MMA_BF16(acc[mt][2 * p + 1], ah[mt][0], ah[mt][1], ah[mt][2], ah[mt][3], bh2, bh3);
            }
            // term Ah*Bl
#pragma unroll
            for (int mt = 0; mt < 2; mt++) {
                MMA_BF16(acc[mt][2 * p],     ah[mt][0], ah[mt][1], ah[mt][2], ah[mt][3], bl0, bl1);
                MMA_BF16(acc[mt][2 * p + 1], ah[mt][0], ah[mt][1], ah[mt][2], ah[mt][3], bl2, bl3);
            }
            // term Al*Bh
#pragma unroll
            for (int mt = 0; mt < 2; mt++) {
                MMA_BF16(acc[mt][2 * p],     al[mt][0], al[mt][1], al[mt][2], al[mt][3], bh0, bh1);
                MMA_BF16(acc[mt][2 * p + 1], al[mt][0], al[mt][1], al[mt][2], al[mt][3], bh2, bh3);
            }
        }

        if (pre) {
            uint32_t h0, l0, h1, l1;
            split_pack(v0.x, v0.y, h0, l0);
            split_pack(v0.z, v0.w, h1, l1);
            *(uint2*)&sm[S_AH + nxt * ABUFB + ar * ASTRB + apc] = make_uint2(h0, h1);
            *(uint2*)&sm[S_AL + nxt * ABUFB + ar * ASTRB + apc] = make_uint2(l0, l1);
            cp_wait0();
            __syncthreads();
        }
    }

    // ---- epilogue: scale row r by dis[r], store
#pragma unroll
    for (int mt = 0; mt < 2; mt++) {
        int r0 = row0 + wm * 32 + mt * 16 + g;
        int r1 = r0 + 8;
        float s0 = (r0 < N_NODES) ? g_dis[r0] : 0.f;
        float s1 = (r1 < N_NODES) ? g_dis[r1] : 0.f;
#pragma unroll
        for (int nt = 0; nt < 4; nt++) {
            int c0 = wn * 32 + nt * 8 + tg * 2;
            if (r0 < N_NODES)
                *(float2*)(Hout + (size_t)r0 * D + c0) =
                    make_float2(acc[mt][nt][0] * s0, acc[mt][nt][1] * s0);
            if (r1 < N_NODES)
                *(float2*)(Hout + (size_t)r1 * D + c0) =
                    make_float2(acc[mt][nt][2] * s1, acc[mt][nt][3] * s1);
        }
    }
}

// ------------------------- aggregation: one warp per node, MLP-8 gather ----
__global__ __launch_bounds__(256) void k_agg(const float* __restrict__ hs,
                                             const float* __restrict__ b,
                                             float* __restrict__ out,
                                             int do_relu) {
    int lane = threadIdx.x & 31;
    int node = blockIdx.x * (blockDim.x >> 5) + (threadIdx.x >> 5);
    if (node >= N_NODES) return;
    int beg = g_rowoff[node], end = g_rowoff[node + 1];
    const float4* __restrict__ h4 = (const float4*)hs;
    float4 acc = h4[(size_t)node * 32 + lane];      // self-loop term
    for (int e0 = beg; e0 < end; e0 += 32) {
        int n = min(32, end - e0);
        int c = (lane < n) ? g_col[e0 + lane] : 0;
        int j = 0;
        for (; j + 8 <= n; j += 8) {
            int cj[8];
#pragma unroll
            for (int u = 0; u < 8; u++) cj[u] = __shfl_sync(0xffffffffu, c, j + u);
            float4 hv[8];
#pragma unroll
            for (int u = 0; u < 8; u++) hv[u] = h4[(size_t)cj[u] * 32 + lane];
#pragma unroll
            for (int u = 0; u < 8; u++) {
                acc.x += hv[u].x; acc.y += hv[u].y;
                acc.z += hv[u].z; acc.w += hv[u].w;
            }
        }
        for (; j < n; j++) {
            int cj = __shfl_sync(0xffffffffu, c, j);
            float4 hv = h4[(size_t)cj * 32 + lane];
            acc.x += hv.x; acc.y += hv.y;
            acc.z += hv.z; acc.w += hv.w;
        }
    }
    float dis = g_dis[node];
    float4 bv = ((const float4*)b)[lane];
    acc.x = acc.x * dis + bv.x; acc.y = acc.y * dis + bv.y;
    acc.z = acc.z * dis + bv.z; acc.w = acc.w * dis + bv.w;
    if (do_relu) {
        acc.x = fmaxf(acc.x, 0.f); acc.y = fmaxf(acc.y, 0.f);
        acc.z = fmaxf(acc.z, 0.f); acc.w = fmaxf(acc.w, 0.f);
    }
    ((float4*)out)[(size_t)node * 32 + lane] = acc;
}

// ------------------------- pooling -----------------------------------------
__device__ __forceinline__ int lower_bound_batch(const int* __restrict__ batch, int g) {
    int lo = 0, hi = N_NODES;
    while (lo < hi) {
        int mid = (lo + hi) >> 1;
        if (batch[mid] < g) lo = mid + 1; else hi = mid;
    }
    return lo;
}

__global__ void k_pool1(const int* __restrict__ batch) {
    int g = blockIdx.x, c = blockIdx.y, t = threadIdx.x;
    int beg = lower_bound_batch(batch, g);
    int end = lower_bound_batch(batch, g + 1);
    int len = end - beg;
    int chunk = (len + POOL_CHUNKS - 1) / POOL_CHUNKS;
    int s = beg + c * chunk;
    int e = min(end, s + chunk);
    float m = -CUDART_INF_F;
    for (int r = s; r < e; r++)
        m = fmaxf(m, g_agg[(size_t)r * D + t]);
    g_pmax[(size_t)(g * POOL_CHUNKS + c) * D + t] = m;
}

__global__ void k_pool2(float* __restrict__ out) {
    int g = blockIdx.x, t = threadIdx.x;
    float m = -CUDART_INF_F;
#pragma unroll
    for (int c = 0; c < POOL_CHUNKS; c++)
        m = fmaxf(m, g_pmax[(size_t)(g * POOL_CHUNKS + c) * D + t]);
    out[(size_t)g * D + t] = m;
}

// ------------------------- launch ------------------------------------------
extern "C" void kernel_launch(void* const* d_in, const int* in_sizes, int n_in,
                              void* d_out, int out_size) {
    const float* x  = (const float*)d_in[0];
    const float* W1 = (const float*)d_in[1];
    const float* b1 = (const float*)d_in[2];
    const float* W2 = (const float*)d_in[3];
    const float* b2 = (const float*)d_in[4];
    const float* W3 = (const float*)d_in[5];
    const float* b3 = (const float*)d_in[6];
    const int* edge_index = (const int*)d_in[7];
    const int* batch = (const int*)d_in[8];
    const int* src = edge_index;
    const int* dst = edge_index + N_EDGES;
    float* out = (float*)d_out;

    float*    h   = nullptr; cudaGetSymbolAddress((void**)&h,   g_h);
    float*    agg = nullptr; cudaGetSymbolAddress((void**)&agg, g_agg);
    uint32_t* wh  = nullptr; cudaGetSymbolAddress((void**)&wh,  g_Wbh);
    uint32_t* wl  = nullptr; cudaGetSymbolAddress((void**)&wl,  g_Wbl);

    const int nthr = 256;
    const int gemm_grid = (N_NODES + 63) / 64;     // 782
    const int agg_grid  = (N_NODES + 7) / 8;
    const int WSZ = 128 * 64;   // u32 per layer

    // g_deg zero on entry: BSS-init first call, k_scan23 re-zeroes each call.
    k_count <<<(N_EDGES + nthr - 1) / nthr, nthr>>>(dst);            // 1
    k_scan1 <<<N_SCAN_BLKS, SCAN_BLK>>>();                            // 2
    k_splitW<<<(3 * WSZ + nthr - 1) / nthr, nthr>>>(W1, W2, W3);      // 3
    k_gemm_tc<<<gemm_grid, 256>>>(x, wh, wl, h);                      // 4 (profiled)
    k_scan23<<<N_SCAN_BLKS, SCAN_BLK>>>();                            // 5
    k_fill  <<<(N_EDGES + nthr - 1) / nthr, nthr>>>(src, dst);        // 6

    k_agg    <<<agg_grid, 256>>>(h, b1, agg, 1);
    k_gemm_tc<<<gemm_grid, 256>>>(agg, wh + WSZ, wl + WSZ, h);
    k_agg    <<<agg_grid, 256>>>(h, b2, agg, 1);
    k_gemm_tc<<<gemm_grid, 256>>>(agg, wh + 2 * WSZ, wl + 2 * WSZ, h);
    k_agg    <<<agg_grid, 256>>>(h, b3, agg, 0);

    k_pool1<<<dim3(N_GRAPHS, POOL_CHUNKS), D>>>(batch);
    k_pool2<<<N_GRAPHS, D>>>(out);
}

// round 14
// speedup vs baseline: 1.0091x; 1.0091x over previous
#include <cuda_runtime.h>
#include <cuda_bf16.h>
#include <math_constants.h>
#include <cstdint>

#define N_NODES 50000
#define N_EDGES 800000
#define D 128
#define N_GRAPHS 64
#define SCAN_BLK 1024
#define N_SCAN_BLKS ((N_NODES + SCAN_BLK - 1) / SCAN_BLK)   // 49
#define POOL_CHUNKS 8

// GEMM smem layout in uint32 units, plain bf16 tiles (ldmatrix-friendly).
// W tile: 16 k-rows x 128 n bf16, row stride 68 u32 (272B = 17*16B: conflict-free)
// A tile: 128 m-rows x 16 k bf16 (8 u32), row stride 12 u32: ldsm conflict-free
#define WSTRB 68
#define WBUFB (16 * WSTRB)       // 1088
#define ASTRB 12
#define ABUFB (128 * ASTRB)      // 1536
#define S_WH 0
#define S_WL (2 * WBUFB)                   // 2176
#define S_AH (4 * WBUFB)                   // 4352
#define S_AL (4 * WBUFB + 2 * ABUFB)       // 7424
#define S_TOT (4 * WBUFB + 4 * ABUFB)      // 10496 u32 = 41984 B

#define WPART (3 * 128 * 64)     // u32 elements in the W-split part

// ------------------------- device scratch ----------------------------------
__device__ float    g_dis[N_NODES];
__device__ int      g_deg[N_NODES];         // zeroed by k_scan23 for next call
__device__ int      g_rowoff[N_NODES + 1];
__device__ int      g_next[N_NODES];
__device__ int      g_bsum[N_SCAN_BLKS];
__device__ int      g_col[N_EDGES];
__device__ float    g_h[N_NODES * D];       // dis-scaled GEMM output (fp32)
__device__ float    g_agg[N_NODES * D];     // layer-3 agg output (for pool)
__device__ float    g_pmax[N_GRAPHS * POOL_CHUNKS * D];
__device__ uint32_t g_Wbh[WPART];           // bf16 hi W, [layer][k][n2]
__device__ uint32_t g_Wbl[WPART];           // bf16 lo W
__device__ uint32_t g_xh[N_NODES * 64];     // bf16 hi of x (k-pairs packed)
__device__ uint32_t g_xl[N_NODES * 64];
__device__ uint32_t g_Ah[N_NODES * 64];     // bf16 hi of agg output (layers 1,2)
__device__ uint32_t g_Al[N_NODES * 64];

// ------------------------- helpers -----------------------------------------
__device__ __forceinline__ void split_pack(float x, float y,
                                           uint32_t& hi, uint32_t& lo) {
    __nv_bfloat162 h2 = __floats2bfloat162_rn(x, y);
    float rx = x - __bfloat162float(h2.x);
    float ry = y - __bfloat162float(h2.y);
    __nv_bfloat162 l2 = __floats2bfloat162_rn(rx, ry);
    hi = *reinterpret_cast<uint32_t*>(&h2);
    lo = *reinterpret_cast<uint32_t*>(&l2);
}

#define MMA_BF16(C, A0, A1, A2, A3, B0, B1)                                   \
    asm volatile(                                                             \
        "mma.sync.aligned.m16n8k16.row.col.f32.bf16.bf16.f32 "                \
        "{%0,%1,%2,%3}, {%4,%5,%6,%7}, {%8,%9}, {%0,%1,%2,%3};"               \
        : "+f"(C[0]), "+f"(C[1]), "+f"(C[2]), "+f"(C[3])                      \
        : "r"(A0), "r"(A1), "r"(A2), "r"(A3), "r"(B0), "r"(B1))

__device__ __forceinline__ void ldsm_x4(uint32_t& r0, uint32_t& r1,
                                        uint32_t& r2, uint32_t& r3,
                                        uint32_t addr) {
    asm volatile("ldmatrix.sync.aligned.m8n8.x4.shared.b16 {%0,%1,%2,%3}, [%4];"
                 : "=r"(r0), "=r"(r1), "=r"(r2), "=r"(r3) : "r"(addr));
}
__device__ __forceinline__ void ldsm_x4_t(uint32_t& r0, uint32_t& r1,
                                          uint32_t& r2, uint32_t& r3,
                                          uint32_t addr) {
    asm volatile("ldmatrix.sync.aligned.m8n8.x4.trans.shared.b16 {%0,%1,%2,%3}, [%4];"
                 : "=r"(r0), "=r"(r1), "=r"(r2), "=r"(r3) : "r"(addr));
}

__device__ __forceinline__ void cp_async16u(uint32_t* dst_smem, const uint32_t* src) {
    unsigned d = (unsigned)__cvta_generic_to_shared(dst_smem);
    asm volatile("cp.async.cg.shared.global [%0], [%1], 16;" :: "r"(d), "l"(src));
}
__device__ __forceinline__ void cp_commit() {
    asm volatile("cp.async.commit_group;");
}
__device__ __forceinline__ void cp_wait0() {
    asm volatile("cp.async.wait_group 0;");
}

// ------------------------- CSR build ---------------------------------------
__global__ void k_count(const int* __restrict__ dst) {
    int i = blockIdx.x * blockDim.x + threadIdx.x;
    if (i < N_EDGES) atomicAdd(&g_deg[dst[i]], 1);
}

__global__ __launch_bounds__(SCAN_BLK) void k_scan1() {
    __shared__ int wsum[32];
    int t = threadIdx.x;
    int lane = t & 31, warp = t >> 5;
    int i = blockIdx.x * SCAN_BLK + t;
    int v = (i < N_NODES) ? g_deg[i] : 0;
    int incl = v;
#pragma unroll
    for (int off = 1; off < 32; off <<= 1) {
        int u = __shfl_up_sync(0xffffffffu, incl, off);
        if (lane >= off) incl += u;
    }
    if (lane == 31) wsum[warp] = incl;
    __syncthreads();
    if (warp == 0) {
        int w = wsum[lane];
        int wi = w;
#pragma unroll
        for (int off = 1; off < 32; off <<= 1) {
            int u = __shfl_up_sync(0xffffffffu, wi, off);
            if (lane >= off) wi += u;
        }
        wsum[lane] = wi - w;
    }
    __syncthreads();
    int inclTot = incl + wsum[warp];
    if (i < N_NODES) {
        g_rowoff[i] = inclTot - v;
        g_dis[i] = rsqrtf((float)v + 1.0f);
    }
    if (t == SCAN_BLK - 1) g_bsum[blockIdx.x] = inclTot;
}

__global__ __launch_bounds__(SCAN_BLK) void k_scan23() {
    __shared__ int s[64];
    int t = threadIdx.x;
    if (t < 64) {
        int v = (t < N_SCAN_BLKS) ? g_bsum[t] : 0;
        s[t] = v;
        __syncthreads();
#pragma unroll
        for (int off = 1; off < 64; off <<= 1) {
            int add = (t >= off) ? s[t - off] : 0;
            __syncthreads();
            s[t] += add;
            __syncthreads();
        }
        int v2 = (t < N_SCAN_BLKS) ? g_bsum[t] : 0;
        s[t] -= v2;
    } else {
        __syncthreads();
#pragma unroll
        for (int off = 1; off < 64; off <<= 1) { __syncthreads(); __syncthreads(); }
    }
    __syncthreads();
    int boff = s[blockIdx.x];
    int i = blockIdx.x * SCAN_BLK + t;
    if (i < N_NODES) {
        int fin = g_rowoff[i] + boff;
        g_rowoff[i] = fin;
        g_next[i] = fin;
        g_deg[i] = 0;
    }
    if (i == 0) g_rowoff[N_NODES] = N_EDGES;
}

__global__ void k_fill(const int* __restrict__ src, const int* __restrict__ dst) {
    int i = blockIdx.x * blockDim.x + threadIdx.x;
    if (i < N_EDGES) {
        int pos = atomicAdd(&g_next[dst[i]], 1);
        g_col[pos] = src[i];
    }
}

// ------------------------- fused split: W (all layers) + x -----------------
// W part: g_Wb*[layer*8192 + k*64 + n2] = bf16x2{ W[k][2n2], W[k][2n2+1] }
// x part: g_x*[node*64 + 2q (+1)] from float4 group q of row node
__global__ void k_split(const float* __restrict__ W1,
                        const float* __restrict__ W2,
                        const float* __restrict__ W3,
                        const float* __restrict__ x) {
    int i = blockIdx.x * blockDim.x + threadIdx.x;
    if (i < WPART) {
        int m = i >> 13, r = i & 8191;
        int k = r >> 6, n2 = r & 63;
        const float* Ws = (m == 0) ? W1 : ((m == 1) ? W2 : W3);
        float x0 = Ws[k * D + 2 * n2];
        float x1 = Ws[k * D + 2 * n2 + 1];
        uint32_t hi, lo;
        split_pack(x0, x1, hi, lo);
        g_Wbh[i] = hi;
        g_Wbl[i] = lo;
    } else {
        int j = i - WPART;
        if (j >= N_NODES * 32) return;
        int node = j >> 5, q = j & 31;
        float4 v = ((const float4*)x)[(size_t)node * 32 + q];
        uint32_t h0, l0, h1, l1;
        split_pack(v.x, v.y, h0, l0);
        split_pack(v.z, v.w, h1, l1);
        *(uint2*)&g_xh[(size_t)node * 64 + q * 2] = make_uint2(h0, h1);
        *(uint2*)&g_xl[(size_t)node * 64 + q * 2] = make_uint2(l0, l1);
    }
}

// ------------------------- pure-cp.async bf16x3 GEMM, M-tile 128 -----------
// 256 threads (8 warps as 4x2: M=32,N=64 per warp), K chunk 16, double-buffer.
// A arrives pre-split (bf16 hi/lo pairs) — no conversion in-kernel.
// Epilogue scales row i by dis[i], stores fp32.
__global__ __launch_bounds__(256, 2) void k_gemm_tc(const uint32_t* __restrict__ Ahg,
                                                    const uint32_t* __restrict__ Alg,
                                                    const uint32_t* __restrict__ Wbh,
                                                    const uint32_t* __restrict__ Wbl,
                                                    float* __restrict__ Hout) {
    __shared__ uint32_t sm[S_TOT];
    int tid  = threadIdx.x;
    int warp = tid >> 5, lane = tid & 31;
    int g = lane >> 2, tg = lane & 3;
    int wm = warp & 3, wn = warp >> 2;          // 4x2 warp grid
    int row0 = blockIdx.x * 128;

    // copy coordinates
    int wrr = tid >> 4, wcc = (tid & 15) * 4;   // W: 16 rows x 64 u32, 1 cp/thread
    int arow = tid >> 1, asub = (tid & 1) * 4;  // A: 128 rows x 8 u32, 2 cps/row
    bool arok = (row0 + arow) < N_NODES;
    const uint32_t* asrc = Ahg + (size_t)(row0 + arow) * 64 + asub;
    const uint32_t* alsrc = Alg + (size_t)(row0 + arow) * 64 + asub;

    // ldmatrix lane addressing
    int rowsel = ((lane >> 3) & 1) * 8 + (lane & 7);
    int half4 = (lane >> 4) * 4;
    uint32_t smb = (uint32_t)__cvta_generic_to_shared(sm);
    uint32_t a_addr[2];
#pragma unroll
    for (int mt = 0; mt < 2; mt++)
        a_addr[mt] = smb + (uint32_t)(S_AH + (wm * 32 + mt * 16 + rowsel) * ASTRB + half4) * 4;
    uint32_t w_addr[4];
#pragma unroll
    for (int p = 0; p < 4; p++)
        w_addr[p] = smb + (uint32_t)(S_WH + rowsel * WSTRB + wn * 32 + p * 8 + half4) * 4;

    const uint32_t ALOFF = (uint32_t)(S_AL - S_AH) * 4;
    const uint32_t WLOFF = (uint32_t)(S_WL - S_WH) * 4;

    float acc[2][8][4];
#pragma unroll
    for (int mt = 0; mt < 2; mt++)
#pragma unroll
        for (int nt = 0; nt < 8; nt++)
#pragma unroll
            for (int c = 0; c < 4; c++) acc[mt][nt][c] = 0.0f;

    // ---- prologue: stage chunk 0 into buffer 0
    cp_async16u(&sm[S_WH + wrr * WSTRB + wcc], Wbh + wrr * 64 + wcc);
    cp_async16u(&sm[S_WL + wrr * WSTRB + wcc], Wbl + wrr * 64 + wcc);
    if (arok) {
        cp_async16u(&sm[S_AH + arow * ASTRB + asub], asrc);
        cp_async16u(&sm[S_AL + arow * ASTRB + asub], alsrc);
    }
    cp_commit();
    cp_wait0();
    __syncthreads();

    for (int kc = 0; kc < 8; kc++) {
        int buf = kc & 1, nxt = buf ^ 1;
        bool pre = (kc < 7);
        if (pre) {
            const uint32_t* wh = Wbh + (kc + 1) * 1024;
            const uint32_t* wl = Wbl + (kc + 1) * 1024;
            cp_async16u(&sm[S_WH + nxt * WBUFB + wrr * WSTRB + wcc], wh + wrr * 64 + wcc);
            cp_async16u(&sm[S_WL + nxt * WBUFB + wrr * WSTRB + wcc], wl + wrr * 64 + wcc);
            if (arok) {
                cp_async16u(&sm[S_AH + nxt * ABUFB + arow * ASTRB + asub], asrc + (kc + 1) * 8);
                cp_async16u(&sm[S_AL + nxt * ABUFB + arow * ASTRB + asub], alsrc + (kc + 1) * 8);
            }
            cp_commit();
        }

        // ---- MMAs on current buffer (one k16 step)
        uint32_t abufo = (uint32_t)(buf * ABUFB) * 4;
        uint32_t wbufo = (uint32_t)(buf * WBUFB) * 4;

        uint32_t ah[2][4], al[2][4];
#pragma unroll
        for (int mt = 0; mt < 2; mt++) {
            ldsm_x4(ah[mt][0], ah[mt][1], ah[mt][2], ah[mt][3], a_addr[mt] + abufo);
            ldsm_x4(al[mt][0], al[mt][1], al[mt][2], al[mt][3], a_addr[mt] + abufo + ALOFF);
        }
#pragma unroll
        for (int p = 0; p < 4; p++) {
            uint32_t bh0, bh1, bh2, bh3, bl0, bl1, bl2, bl3;
            ldsm_x4_t(bh0, bh1, bh2, bh3, w_addr[p] + wbufo);
            ldsm_x4_t(bl0, bl1, bl2, bl3, w_addr[p] + wbufo + WLOFF);
            // 4 independent accumulators between dependent reuses
            MMA_BF16(acc[0][2 * p],     ah[0][0], ah[0][1], ah[0][2], ah[0][3], bh0, bh1);
            MMA_BF16(acc[1][2 * p],     ah[1][0], ah[1][1], ah[1][2], ah[1][3], bh0, bh1);
            MMA_BF16(acc[0][2 * p + 1], ah[0][0], ah[0][1], ah[0][2], ah[0][3], bh2, bh3);
            MMA_BF16(acc[1][2 * p + 1], ah[1][0], ah[1][1], ah[1][2], ah[1][3], bh2, bh3);
            MMA_BF16(acc[0][2 * p],     ah[0][0], ah[0][1], ah[0][2], ah[0][3], bl0, bl1);
            MMA_BF16(acc[1][2 * p],     ah[1][0], ah[1][1], ah[1][2], ah[1][3], bl0, bl1);
            MMA_BF16(acc[0][2 * p + 1], ah[0][0], ah[0][1], ah[0][2], ah[0][3], bl2, bl3);
            MMA_BF16(acc[1][2 * p + 1], ah[1][0], ah[1][1], ah[1][2], ah[1][3], bl2, bl3);
            MMA_BF16(acc[0][2 * p],     al[0][0], al[0][1], al[0][2], al[0][3], bh0, bh1);
            MMA_BF16(acc[1][2 * p],     al[1][0], al[1][1], al[1][2], al[1][3], bh0, bh1);
            MMA_BF16(acc[0][2 * p + 1], al[0][0], al[0][1], al[0][2], al[0][3], bh2, bh3);
            MMA_BF16(acc[1][2 * p + 1], al[1][0], al[1][1], al[1][2], al[1][3], bh2, bh3);
        }

        if (pre) {
            cp_wait0();
            __syncthreads();
        }
    }

    // ---- epilogue: scale row r by dis[r], store fp32
#pragma unroll
    for (int mt = 0; mt < 2; mt++) {
        int r0 = row0 + wm * 32 + mt * 16 + g;
        int r1 = r0 + 8;
        float s0 = (r0 < N_NODES) ? g_dis[r0] : 0.f;
        float s1 = (r1 < N_NODES) ? g_dis[r1] : 0.f;
#pragma unroll
        for (int nt = 0; nt < 8; nt++) {
            int c0 = wn * 64 + nt * 8 + tg * 2;
            if (r0 < N_NODES)
                *(float2*)(Hout + (size_t)r0 * D + c0) =
                    make_float2(acc[mt][nt][0] * s0, acc[mt][nt][1] * s0);
            if (r1 < N_NODES)
                *(float2*)(Hout + (size_t)r1 * D + c0) =
                    make_float2(acc[mt][nt][2] * s1, acc[mt][nt][3] * s1);
        }
    }
}

// ------------------------- aggregation: one warp per node ------------------
// mode 1: ReLU then write bf16 hi/lo pairs (feeds next GEMM).
// mode 0: write fp32 (feeds pool).
__global__ __launch_bounds__(256) void k_agg(const float* __restrict__ hs,
                                             const float* __restrict__ b,
                                             float* __restrict__ outf,
                                             uint32_t* __restrict__ oh,
                                             uint32_t* __restrict__ ol,
                                             int mode) {
    int lane = threadIdx.x & 31;
    int node = blockIdx.x * (blockDim.x >> 5) + (threadIdx.x >> 5);
    if (node >= N_NODES) return;
    int beg = g_rowoff[node], end = g_rowoff[node + 1];
    const float4* __restrict__ h4 = (const float4*)hs;
    float4 acc = h4[(size_t)node * 32 + lane];      // self-loop term
    for (int e0 = beg; e0 < end; e0 += 32) {
        int n = min(32, end - e0);
        int c = (lane < n) ? g_col[e0 + lane] : 0;
        int j = 0;
        for (; j + 8 <= n; j += 8) {
            int cj[8];
#pragma unroll
            for (int u = 0; u < 8; u++) cj[u] = __shfl_sync(0xffffffffu, c, j + u);
            float4 hv[8];
#pragma unroll
            for (int u = 0; u < 8; u++) hv[u] = h4[(size_t)cj[u] * 32 + lane];
#pragma unroll
            for (int u = 0; u < 8; u++) {
                acc.x += hv[u].x; acc.y += hv[u].y;
                acc.z += hv[u].z; acc.w += hv[u].w;
            }
        }
        for (; j < n; j++) {
            int cj = __shfl_sync(0xffffffffu, c, j);
            float4 hv = h4[(size_t)cj * 32 + lane];
            acc.x += hv.x; acc.y += hv.y;
            acc.z += hv.z; acc.w += hv.w;
        }
    }
    float dis = g_dis[node];
    float4 bv = ((const float4*)b)[lane];
    acc.x = acc.x * dis + bv.x; acc.y = acc.y * dis + bv.y;
    acc.z = acc.z * dis + bv.z; acc.w = acc.w * dis + bv.w;
    if (mode) {
        acc.x = fmaxf(acc.x, 0.f); acc.y = fmaxf(acc.y, 0.f);
        acc.z = fmaxf(acc.z, 0.f); acc.w = fmaxf(acc.w, 0.f);
        uint32_t h0, l0, h1, l1;
        split_pack(acc.x, acc.y, h0, l0);
        split_pack(acc.z, acc.w, h1, l1);
        *(uint2*)&oh[(size_t)node * 64 + lane * 2] = make_uint2(h0, h1);
        *(uint2*)&ol[(size_t)node * 64 + lane * 2] = make_uint2(l0, l1);
    } else {
        ((float4*)outf)[(size_t)node * 32 + lane] = acc;
    }
}

// ------------------------- pooling -----------------------------------------
__device__ __forceinline__ int lower_bound_batch(const int* __restrict__ batch, int g) {
    int lo = 0, hi = N_NODES;
    while (lo < hi) {
        int mid = (lo + hi) >> 1;
        if (batch[mid] < g) lo = mid + 1; else hi = mid;
    }
    return lo;
}

__global__ void k_pool1(const int* __restrict__ batch) {
    int g = blockIdx.x, c = blockIdx.y, t = threadIdx.x;
    int beg = lower_bound_batch(batch, g);
    int end = lower_bound_batch(batch, g + 1);
    int len = end - beg;
    int chunk = (len + POOL_CHUNKS - 1) / POOL_CHUNKS;
    int s = beg + c * chunk;
    int e = min(end, s + chunk);
    float m = -CUDART_INF_F;
    for (int r = s; r < e; r++)
        m = fmaxf(m, g_agg[(size_t)r * D + t]);
    g_pmax[(size_t)(g * POOL_CHUNKS + c) * D + t] = m;
}

__global__ void k_pool2(float* __restrict__ out) {
    int g = blockIdx.x, t = threadIdx.x;
    float m = -CUDART_INF_F;
#pragma unroll
    for (int c = 0; c < POOL_CHUNKS; c++)
        m = fmaxf(m, g_pmax[(size_t)(g * POOL_CHUNKS + c) * D + t]);
    out[(size_t)g * D + t] = m;
}

// ------------------------- launch ------------------------------------------
extern "C" void kernel_launch(void* const* d_in, const int* in_sizes, int n_in,
                              void* d_out, int out_size) {
    const float* x  = (const float*)d_in[0];
    const float* W1 = (const float*)d_in[1];
    const float* b1 = (const float*)d_in[2];
    const float* W2 = (const float*)d_in[3];
    const float* b2 = (const float*)d_in[4];
    const float* W3 = (const float*)d_in[5];
    const float* b3 = (const float*)d_in[6];
    const int* edge_index = (const int*)d_in[7];
    const int* batch = (const int*)d_in[8];
    const int* src = edge_index;
    const int* dst = edge_index + N_EDGES;
    float* out = (float*)d_out;

    float*    h   = nullptr; cudaGetSymbolAddress((void**)&h,   g_h);
    float*    agg = nullptr; cudaGetSymbolAddress((void**)&agg, g_agg);
    uint32_t* wbh = nullptr; cudaGetSymbolAddress((void**)&wbh, g_Wbh);
    uint32_t* wbl = nullptr; cudaGetSymbolAddress((void**)&wbl, g_Wbl);
    uint32_t* xh  = nullptr; cudaGetSymbolAddress((void**)&xh,  g_xh);
    uint32_t* xl  = nullptr; cudaGetSymbolAddress((void**)&xl,  g_xl);
    uint32_t* ah  = nullptr; cudaGetSymbolAddress((void**)&ah,  g_Ah);
    uint32_t* al  = nullptr; cudaGetSymbolAddress((void**)&al,  g_Al);

    const int nthr = 256;
    const int gemm_grid = (N_NODES + 127) / 128;   // 391
    const int agg_grid  = (N_NODES + 7) / 8;
    const int WSZ = 128 * 64;                      // u32 per layer
    const int split_n = WPART + N_NODES * 32;

    // g_deg zero on entry: BSS-init first call, k_scan23 re-zeroes each call.
    k_count <<<(N_EDGES + nthr - 1) / nthr, nthr>>>(dst);            // 1
    k_scan1 <<<N_SCAN_BLKS, SCAN_BLK>>>();                            // 2
    k_split <<<(split_n + nthr - 1) / nthr, nthr>>>(W1, W2, W3, x);   // 3
    k_gemm_tc<<<gemm_grid, 256>>>(xh, xl, wbh, wbl, h);               // 4 (profiled)
    k_scan23<<<N_SCAN_BLKS, SCAN_BLK>>>();                            // 5
    k_fill  <<<(N_EDGES + nthr - 1) / nthr, nthr>>>(src, dst);        // 6

    k_agg    <<<agg_grid, 256>>>(h, b1, nullptr, ah, al, 1);
    k_gemm_tc<<<gemm_grid, 256>>>(ah, al, wbh + WSZ, wbl + WSZ, h);
    k_agg    <<<agg_grid, 256>>>(h, b2, nullptr, ah, al, 1);
    k_gemm_tc<<<gemm_grid, 256>>>(ah, al, wbh + 2 * WSZ, wbl + 2 * WSZ, h);
    k_agg    <<<agg_grid, 256>>>(h, b3, agg, nullptr, nullptr, 0);

    k_pool1<<<dim3(N_GRAPHS, POOL_CHUNKS), D>>>(batch);
    k_pool2<<<N_GRAPHS, D>>>(out);
}

// round 15
// speedup vs baseline: 1.1876x; 1.1769x over previous
#include <cuda_runtime.h>
#include <cuda_bf16.h>
#include <cuda_fp16.h>
#include <math_constants.h>
#include <cstdint>

#define N_NODES 50000
#define N_EDGES 800000
#define D 128
#define N_GRAPHS 64
#define SCAN_BLK 1024
#define N_SCAN_BLKS ((N_NODES + SCAN_BLK - 1) / SCAN_BLK)   // 49
#define POOL_CHUNKS 8

// GEMM smem layout in uint32 units, plain bf16 tiles (ldmatrix-friendly).
#define WSTRB 68
#define WBUFB (16 * WSTRB)       // 1088
#define ASTRB 12
#define ABUFB (128 * ASTRB)      // 1536
#define S_WH 0
#define S_WL (2 * WBUFB)
#define S_AH (4 * WBUFB)
#define S_AL (4 * WBUFB + 2 * ABUFB)
#define S_TOT (4 * WBUFB + 4 * ABUFB)      // 10496 u32 = 41984 B

// ------------------------- device scratch ----------------------------------
__device__ float    g_dis[N_NODES];
__device__ int      g_deg[N_NODES];         // zeroed by k_scan23 for next call
__device__ int      g_rowoff[N_NODES + 1];
__device__ int      g_next[N_NODES];
__device__ int      g_bsum[N_SCAN_BLKS];
__device__ int      g_col[N_EDGES];
__device__ uint32_t g_h16[N_NODES * 64];    // dis-scaled GEMM output, half2 packed
__device__ float    g_agg[N_NODES * D];     // agg output (fp32, feeds GEMM/pool)
__device__ float    g_pmax[N_GRAPHS * POOL_CHUNKS * D];
__device__ uint32_t g_Wbh[3 * 128 * 64];    // plain bf16 hi W, [layer][k][n2]
__device__ uint32_t g_Wbl[3 * 128 * 64];    // plain bf16 lo W

// ------------------------- helpers -----------------------------------------
__device__ __forceinline__ void split_pack(float x, float y,
                                           uint32_t& hi, uint32_t& lo) {
    __nv_bfloat162 h2 = __floats2bfloat162_rn(x, y);
    float rx = x - __bfloat162float(h2.x);
    float ry = y - __bfloat162float(h2.y);
    __nv_bfloat162 l2 = __floats2bfloat162_rn(rx, ry);
    hi = *reinterpret_cast<uint32_t*>(&h2);
    lo = *reinterpret_cast<uint32_t*>(&l2);
}

__device__ __forceinline__ uint32_t pack_h2(float a, float b) {
    __half2 h = __floats2half2_rn(a, b);
    return *reinterpret_cast<uint32_t*>(&h);
}

#define MMA_BF16(C, A0, A1, A2, A3, B0, B1)                                   \
    asm volatile(                                                             \
        "mma.sync.aligned.m16n8k16.row.col.f32.bf16.bf16.f32 "                \
        "{%0,%1,%2,%3}, {%4,%5,%6,%7}, {%8,%9}, {%0,%1,%2,%3};"               \
        : "+f"(C[0]), "+f"(C[1]), "+f"(C[2]), "+f"(C[3])                      \
        : "r"(A0), "r"(A1), "r"(A2), "r"(A3), "r"(B0), "r"(B1))

__device__ __forceinline__ void ldsm_x4(uint32_t& r0, uint32_t& r1,
                                        uint32_t& r2, uint32_t& r3,
                                        uint32_t addr) {
    asm volatile("ldmatrix.sync.aligned.m8n8.x4.shared.b16 {%0,%1,%2,%3}, [%4];"
                 : "=r"(r0), "=r"(r1), "=r"(r2), "=r"(r3) : "r"(addr));
}
__device__ __forceinline__ void ldsm_x4_t(uint32_t& r0, uint32_t& r1,
                                          uint32_t& r2, uint32_t& r3,
                                          uint32_t addr) {
    asm volatile("ldmatrix.sync.aligned.m8n8.x4.trans.shared.b16 {%0,%1,%2,%3}, [%4];"
                 : "=r"(r0), "=r"(r1), "=r"(r2), "=r"(r3) : "r"(addr));
}

__device__ __forceinline__ void cp_async16u(uint32_t* dst_smem, const uint32_t* src) {
    unsigned d = (unsigned)__cvta_generic_to_shared(dst_smem);
    asm volatile("cp.async.cg.shared.global [%0], [%1], 16;" :: "r"(d), "l"(src));
}
__device__ __forceinline__ void cp_commit() {
    asm volatile("cp.async.commit_group;");
}
__device__ __forceinline__ void cp_wait0() {
    asm volatile("cp.async.wait_group 0;");
}

// ------------------------- CSR build ---------------------------------------
__global__ void k_count(const int* __restrict__ dst) {
    int i = blockIdx.x * blockDim.x + threadIdx.x;
    if (i < N_EDGES) atomicAdd(&g_deg[dst[i]], 1);
}

__global__ __launch_bounds__(SCAN_BLK) void k_scan1() {
    __shared__ int wsum[32];
    int t = threadIdx.x;
    int lane = t & 31, warp = t >> 5;
    int i = blockIdx.x * SCAN_BLK + t;
    int v = (i < N_NODES) ? g_deg[i] : 0;
    int incl = v;
#pragma unroll
    for (int off = 1; off < 32; off <<= 1) {
        int u = __shfl_up_sync(0xffffffffu, incl, off);
        if (lane >= off) incl += u;
    }
    if (lane == 31) wsum[warp] = incl;
    __syncthreads();
    if (warp == 0) {
        int w = wsum[lane];
        int wi = w;
#pragma unroll
        for (int off = 1; off < 32; off <<= 1) {
            int u = __shfl_up_sync(0xffffffffu, wi, off);
            if (lane >= off) wi += u;
        }
        wsum[lane] = wi - w;
    }
    __syncthreads();
    int inclTot = incl + wsum[warp];
    if (i < N_NODES) {
        g_rowoff[i] = inclTot - v;
        g_dis[i] = rsqrtf((float)v + 1.0f);
    }
    if (t == SCAN_BLK - 1) g_bsum[blockIdx.x] = inclTot;
}

__global__ __launch_bounds__(SCAN_BLK) void k_scan23() {
    __shared__ int s[64];
    int t = threadIdx.x;
    if (t < 64) {
        int v = (t < N_SCAN_BLKS) ? g_bsum[t] : 0;
        s[t] = v;
        __syncthreads();
#pragma unroll
        for (int off = 1; off < 64; off <<= 1) {
            int add = (t >= off) ? s[t - off] : 0;
            __syncthreads();
            s[t] += add;
            __syncthreads();
        }
        int v2 = (t < N_SCAN_BLKS) ? g_bsum[t] : 0;
        s[t] -= v2;
    } else {
        __syncthreads();
#pragma unroll
        for (int off = 1; off < 64; off <<= 1) { __syncthreads(); __syncthreads(); }
    }
    __syncthreads();
    int boff = s[blockIdx.x];
    int i = blockIdx.x * SCAN_BLK + t;
    if (i < N_NODES) {
        int fin = g_rowoff[i] + boff;
        g_rowoff[i] = fin;
        g_next[i] = fin;
        g_deg[i] = 0;
    }
    if (i == 0) g_rowoff[N_NODES] = N_EDGES;
}

__global__ void k_fill(const int* __restrict__ src, const int* __restrict__ dst) {
    int i = blockIdx.x * blockDim.x + threadIdx.x;
    if (i < N_EDGES) {
        int pos = atomicAdd(&g_next[dst[i]], 1);
        g_col[pos] = src[i];
    }
}

// ------------------------- weight pre-split (plain bf16 hi/lo) -------------
__global__ void k_splitW(const float* __restrict__ W1,
                         const float* __restrict__ W2,
                         const float* __restrict__ W3) {
    int i = blockIdx.x * blockDim.x + threadIdx.x;     // 0..24575
    if (i >= 3 * 128 * 64) return;
    int m = i >> 13, r = i & 8191;
    int k = r >> 6, n2 = r & 63;
    const float* Ws = (m == 0) ? W1 : ((m == 1) ? W2 : W3);
    float x0 = Ws[k * D + 2 * n2];
    float x1 = Ws[k * D + 2 * n2 + 1];
    uint32_t hi, lo;
    split_pack(x0, x1, hi, lo);
    g_Wbh[i] = hi;
    g_Wbl[i] = lo;
}

// ------------------------- pipelined bf16x3 GEMM (R10 shape), fp16 out -----
// 256 threads (8 warps as 4x2: M=32,N=64 per warp), M-tile 128, K chunk 16,
// double-buffered (cp.async W, register-staged A split in-kernel).
// Epilogue scales row i by dis[i] and stores half2-packed h.
__global__ __launch_bounds__(256, 2) void k_gemm_tc(const float* __restrict__ A,
                                                    const uint32_t* __restrict__ Wbh,
                                                    const uint32_t* __restrict__ Wbl,
                                                    uint32_t* __restrict__ H16) {
    __shared__ uint32_t sm[S_TOT];
    int tid  = threadIdx.x;
    int warp = tid >> 5, lane = tid & 31;
    int g = lane >> 2, tg = lane & 3;
    int wm = warp & 3, wn = warp >> 2;          // 4x2 warp grid
    int row0 = blockIdx.x * 128;

    // copy coordinates
    int wrr = tid >> 4, wcc = (tid & 15) * 4;   // W: 16 rows x 64 u32
    int ar = tid >> 2;                           // A rows ar, ar+64
    int afc = (tid & 3) * 4;
    int apc = (tid & 3) * 2;

    // ldmatrix lane addressing
    int rowsel = ((lane >> 3) & 1) * 8 + (lane & 7);
    int half4 = (lane >> 4) * 4;
    uint32_t smb = (uint32_t)__cvta_generic_to_shared(sm);
    uint32_t a_addr[2];
#pragma unroll
    for (int mt = 0; mt < 2; mt++)
        a_addr[mt] = smb + (uint32_t)(S_AH + (wm * 32 + mt * 16 + rowsel) * ASTRB + half4) * 4;
    uint32_t w_addr[4];
#pragma unroll
    for (int p = 0; p < 4; p++)
        w_addr[p] = smb + (uint32_t)(S_WH + rowsel * WSTRB + wn * 32 + p * 8 + half4) * 4;

    const uint32_t ALOFF = (uint32_t)(S_AL - S_AH) * 4;
    const uint32_t WLOFF = (uint32_t)(S_WL - S_WH) * 4;

    float acc[2][8][4];
#pragma unroll
    for (int mt = 0; mt < 2; mt++)
#pragma unroll
        for (int nt = 0; nt < 8; nt++)
#pragma unroll
            for (int c = 0; c < 4; c++) acc[mt][nt][c] = 0.0f;

    // ---- prologue: stage chunk 0 into buffer 0
    cp_async16u(&sm[S_WH + wrr * WSTRB + wcc], Wbh + wrr * 64 + wcc);
    cp_async16u(&sm[S_WL + wrr * WSTRB + wcc], Wbl + wrr * 64 + wcc);
    cp_commit();
#pragma unroll
    for (int p = 0; p < 2; p++) {
        int rr = ar + p * 64;
        int gr = row0 + rr;
        float4 v = make_float4(0.f, 0.f, 0.f, 0.f);
        if (gr < N_NODES) v = *(const float4*)(A + (size_t)gr * D + afc);
        uint32_t h0, l0, h1, l1;
        split_pack(v.x, v.y, h0, l0);
        split_pack(v.z, v.w, h1, l1);
        *(uint2*)&sm[S_AH + rr * ASTRB + apc] = make_uint2(h0, h1);
        *(uint2*)&sm[S_AL + rr * ASTRB + apc] = make_uint2(l0, l1);
    }
    cp_wait0();
    __syncthreads();

    for (int kc = 0; kc < 8; kc++) {
        int buf = kc & 1, nxt = buf ^ 1;
        bool pre = (kc < 7);
        float4 v0, v1;
        if (pre) {
            const uint32_t* wh = Wbh + (kc + 1) * 1024;
            const uint32_t* wl = Wbl + (kc + 1) * 1024;
            cp_async16u(&sm[S_WH + nxt * WBUFB + wrr * WSTRB + wcc], wh + wrr * 64 + wcc);
            cp_async16u(&sm[S_WL + nxt * WBUFB + wrr * WSTRB + wcc], wl + wrr * 64 + wcc);
            cp_commit();
            int kcol = (kc + 1) * 16 + afc;
            v0 = make_float4(0.f, 0.f, 0.f, 0.f); v1 = v0;
            int gr0 = row0 + ar, gr1 = gr0 + 64;
            if (gr0 < N_NODES) v0 = *(const float4*)(A + (size_t)gr0 * D + kcol);
            if (gr1 < N_NODES) v1 = *(const float4*)(A + (size_t)gr1 * D + kcol);
        }

        uint32_t abufo = (uint32_t)(buf * ABUFB) * 4;
        uint32_t wbufo = (uint32_t)(buf * WBUFB) * 4;

        uint32_t ah[2][4], al[2][4];
#pragma unroll
        for (int mt = 0; mt < 2; mt++) {
            ldsm_x4(ah[mt][0], ah[mt][1], ah[mt][2], ah[mt][3], a_addr[mt] + abufo);
            ldsm_x4(al[mt][0], al[mt][1], al[mt][2], al[mt][3], a_addr[mt] + abufo + ALOFF);
        }
#pragma unroll
        for (int p = 0; p < 4; p++) {
            uint32_t bh0, bh1, bh2, bh3, bl0, bl1, bl2, bl3;
            ldsm_x4_t(bh0, bh1, bh2, bh3, w_addr[p] + wbufo);
            ldsm_x4_t(bl0, bl1, bl2, bl3, w_addr[p] + wbufo + WLOFF);
            MMA_BF16(acc[0][2 * p],     ah[0][0], ah[0][1], ah[0][2], ah[0][3], bh0, bh1);
            MMA_BF16(acc[1][2 * p],     ah[1][0], ah[1][1], ah[1][2], ah[1][3], bh0, bh1);
            MMA_BF16(acc[0][2 * p + 1], ah[0][0], ah[0][1], ah[0][2], ah[0][3], bh2, bh3);
            MMA_BF16(acc[1][2 * p + 1], ah[1][0], ah[1][1], ah[1][2], ah[1][3], bh2, bh3);
            MMA_BF16(acc[0][2 * p],     ah[0][0], ah[0][1], ah[0][2], ah[0][3], bl0, bl1);
            MMA_BF16(acc[1][2 * p],     ah[1][0], ah[1][1], ah[1][2], ah[1][3], bl0, bl1);
            MMA_BF16(acc[0][2 * p + 1], ah[0][0], ah[0][1], ah[0][2], ah[0][3], bl2, bl3);
            MMA_BF16(acc[1][2 * p + 1], ah[1][0], ah[1][1], ah[1][2], ah[1][3], bl2, bl3);
            MMA_BF16(acc[0][2 * p],     al[0][0], al[0][1], al[0][2], al[0][3], bh0, bh1);
            MMA_BF16(acc[1][2 * p],     al[1][0], al[1][1], al[1][2], al[1][3], bh0, bh1);
            MMA_BF16(acc[0][2 * p + 1], al[0][0], al[0][1], al[0][2], al[0][3], bh2, bh3);
            MMA_BF16(acc[1][2 * p + 1], al[1][0], al[1][1], al[1][2], al[1][3], bh2, bh3);
        }

        if (pre) {
            uint32_t h0, l0, h1, l1;
            split_pack(v0.x, v0.y, h0, l0);
            split_pack(v0.z, v0.w, h1, l1);
            *(uint2*)&sm[S_AH + nxt * ABUFB + ar * ASTRB + apc] = make_uint2(h0, h1);
            *(uint2*)&sm[S_AL + nxt * ABUFB + ar * ASTRB + apc] = make_uint2(l0, l1);
            split_pack(v1.x, v1.y, h0, l0);
            split_pack(v1.z, v1.w, h1, l1);
            *(uint2*)&sm[S_AH + nxt * ABUFB + (ar + 64) * ASTRB + apc] = make_uint2(h0, h1);
            *(uint2*)&sm[S_AL + nxt * ABUFB + (ar + 64) * ASTRB + apc] = make_uint2(l0, l1);
            cp_wait0();
            __syncthreads();
        }
    }

    // ---- epilogue: scale row r by dis[r], store half2 pairs
#pragma unroll
    for (int mt = 0; mt < 2; mt++) {
        int r0 = row0 + wm * 32 + mt * 16 + g;
        int r1 = r0 + 8;
        float s0 = (r0 < N_NODES) ? g_dis[r0] : 0.f;
        float s1 = (r1 < N_NODES) ? g_dis[r1] : 0.f;
#pragma unroll
        for (int nt = 0; nt < 8; nt++) {
            int cp2 = wn * 32 + nt * 4 + tg;      // half2 column index
            if (r0 < N_NODES)
                H16[(size_t)r0 * 64 + cp2] = pack_h2(acc[mt][nt][0] * s0,
                                                     acc[mt][nt][1] * s0);
            if (r1 < N_NODES)
                H16[(size_t)r1 * 64 + cp2] = pack_h2(acc[mt][nt][2] * s1,
                                                     acc[mt][nt][3] * s1);
        }
    }
}

// ------------------------- aggregation: one warp per node, fp16 gather -----
// out_i = dis_i * (sum_e h[col_e] + h_i) + b  (ReLU optional), fp32 out.
__global__ __launch_bounds__(256) void k_agg(const uint32_t* __restrict__ h16,
                                             const float* __restrict__ b,
                                             float* __restrict__ out,
                                             int do_relu) {
    int lane = threadIdx.x & 31;
    int node = blockIdx.x * (blockDim.x >> 5) + (threadIdx.x >> 5);
    if (node >= N_NODES) return;
    int beg = g_rowoff[node], end = g_rowoff[node + 1];
    const uint2* __restrict__ hp = (const uint2*)h16;   // 4 halves per uint2
    // self term
    float4 acc;
    {
        uint2 v = hp[(size_t)node * 32 + lane];
        __half2 a = *reinterpret_cast<__half2*>(&v.x);
        __half2 c = *reinterpret_cast<__half2*>(&v.y);
        float2 fa = __half22float2(a), fc = __half22float2(c);
        acc = make_float4(fa.x, fa.y, fc.x, fc.y);
    }
    for (int e0 = beg; e0 < end; e0 += 32) {
        int n = min(32, end - e0);
        int c = (lane < n) ? g_col[e0 + lane] : 0;
        int j = 0;
        for (; j + 8 <= n; j += 8) {
            int cj[8];
#pragma unroll
            for (int u = 0; u < 8; u++) cj[u] = __shfl_sync(0xffffffffu, c, j + u);
            uint2 hv[8];
#pragma unroll
            for (int u = 0; u < 8; u++) hv[u] = hp[(size_t)cj[u] * 32 + lane];
#pragma unroll
            for (int u = 0; u < 8; u++) {
                __half2 a = *reinterpret_cast<__half2*>(&hv[u].x);
                __half2 d = *reinterpret_cast<__half2*>(&hv[u].y);
                float2 fa = __half22float2(a), fd = __half22float2(d);
                acc.x += fa.x; acc.y += fa.y;
                acc.z += fd.x; acc.w += fd.y;
            }
        }
        for (; j < n; j++) {
            int cj = __shfl_sync(0xffffffffu, c, j);
            uint2 v = hp[(size_t)cj * 32 + lane];
            __half2 a = *reinterpret_cast<__half2*>(&v.x);
            __half2 d = *reinterpret_cast<__half2*>(&v.y);
            float2 fa = __half22float2(a), fd = __half22float2(d);
            acc.x += fa.x; acc.y += fa.y;
            acc.z += fd.x; acc.w += fd.y;
        }
    }
    float dis = g_dis[node];
    float4 bv = ((const float4*)b)[lane];
    acc.x = acc.x * dis + bv.x; acc.y = acc.y * dis + bv.y;
    acc.z = acc.z * dis + bv.z; acc.w = acc.w * dis + bv.w;
    if (do_relu) {
        acc.x = fmaxf(acc.x, 0.f); acc.y = fmaxf(acc.y, 0.f);
        acc.z = fmaxf(acc.z, 0.f); acc.w = fmaxf(acc.w, 0.f);
    }
    ((float4*)out)[(size_t)node * 32 + lane] = acc;
}

// ------------------------- pooling -----------------------------------------
__device__ __forceinline__ int lower_bound_batch(const int* __restrict__ batch, int g) {
    int lo = 0, hi = N_NODES;
    while (lo < hi) {
        int mid = (lo + hi) >> 1;
        if (batch[mid] < g) lo = mid + 1; else hi = mid;
    }
    return lo;
}

__global__ void k_pool1(const int* __restrict__ batch) {
    int g = blockIdx.x, c = blockIdx.y, t = threadIdx.x;
    int beg = lower_bound_batch(batch, g);
    int end = lower_bound_batch(batch, g + 1);
    int len = end - beg;
    int chunk = (len + POOL_CHUNKS - 1) / POOL_CHUNKS;
    int s = beg + c * chunk;
    int e = min(end, s + chunk);
    float m = -CUDART_INF_F;
    for (int r = s; r < e; r++)
        m = fmaxf(m, g_agg[(size_t)r * D + t]);
    g_pmax[(size_t)(g * POOL_CHUNKS + c) * D + t] = m;
}

__global__ void k_pool2(float* __restrict__ out) {
    int g = blockIdx.x, t = threadIdx.x;
    float m = -CUDART_INF_F;
#pragma unroll
    for (int c = 0; c < POOL_CHUNKS; c++)
        m = fmaxf(m, g_pmax[(size_t)(g * POOL_CHUNKS + c) * D + t]);
    out[(size_t)g * D + t] = m;
}

// ------------------------- launch ------------------------------------------
extern "C" void kernel_launch(void* const* d_in, const int* in_sizes, int n_in,
                              void* d_out, int out_size) {
    const float* x  = (const float*)d_in[0];
    const float* W1 = (const float*)d_in[1];
    const float* b1 = (const float*)d_in[2];
    const float* W2 = (const float*)d_in[3];
    const float* b2 = (const float*)d_in[4];
    const float* W3 = (const float*)d_in[5];
    const float* b3 = (const float*)d_in[6];
    const int* edge_index = (const int*)d_in[7];
    const int* batch = (const int*)d_in[8];
    const int* src = edge_index;
    const int* dst = edge_index + N_EDGES;
    float* out = (float*)d_out;

    uint32_t* h16 = nullptr; cudaGetSymbolAddress((void**)&h16, g_h16);
    float*    agg = nullptr; cudaGetSymbolAddress((void**)&agg, g_agg);
    uint32_t* wbh = nullptr; cudaGetSymbolAddress((void**)&wbh, g_Wbh);
    uint32_t* wbl = nullptr; cudaGetSymbolAddress((void**)&wbl, g_Wbl);

    // side stream + fork/join events, created once on the (uncaptured)
    // correctness call; every call records an identical graph topology.
    static cudaStream_t s2 = nullptr;
    static cudaEvent_t ev_begin = nullptr, ev_dis = nullptr, ev_g1 = nullptr;
    if (s2 == nullptr) {
        cudaStreamCreateWithFlags(&s2, cudaStreamNonBlocking);
        cudaEventCreateWithFlags(&ev_begin, cudaEventDisableTiming);
        cudaEventCreateWithFlags(&ev_dis,   cudaEventDisableTiming);
        cudaEventCreateWithFlags(&ev_g1,    cudaEventDisableTiming);
    }

    const int nthr = 256;
    const int gemm_grid = (N_NODES + 127) / 128;   // 391
    const int agg_grid  = (N_NODES + 7) / 8;
    const int WSZ = 128 * 64;                      // u32 per layer

    // ---- fork: side stream does W-split while main does count/scan
    cudaEventRecord(ev_begin, 0);
    cudaStreamWaitEvent(s2, ev_begin, 0);
    k_splitW<<<(3 * WSZ + nthr - 1) / nthr, nthr, 0, s2>>>(W1, W2, W3);

    // main: CSR chain. g_deg zero on entry (BSS first call; k_scan23 re-zeroes).
    k_count <<<(N_EDGES + nthr - 1) / nthr, nthr>>>(dst);
    k_scan1 <<<N_SCAN_BLKS, SCAN_BLK>>>();
    cudaEventRecord(ev_dis, 0);                   // g_dis ready
    k_scan23<<<N_SCAN_BLKS, SCAN_BLK>>>();
    k_fill  <<<(N_EDGES + nthr - 1) / nthr, nthr>>>(src, dst);

    // side: gemm1 (needs splitW + g_dis), overlaps scan23+fill
    cudaStreamWaitEvent(s2, ev_dis, 0);
    k_gemm_tc<<<gemm_grid, 256, 0, s2>>>(x, wbh, wbl, h16);
    cudaEventRecord(ev_g1, s2);
    cudaStreamWaitEvent(0, ev_g1, 0);             // join

    // serial layer chain on main stream
    k_agg    <<<agg_grid, 256>>>(h16, b1, agg, 1);
    k_gemm_tc<<<gemm_grid, 256>>>(agg, wbh + WSZ, wbl + WSZ, h16);
    k_agg    <<<agg_grid, 256>>>(h16, b2, agg, 1);
    k_gemm_tc<<<gemm_grid, 256>>>(agg, wbh + 2 * WSZ, wbl + 2 * WSZ, h16);
    k_agg    <<<agg_grid, 256>>>(h16, b3, agg, 0);

    k_pool1<<<dim3(N_GRAPHS, POOL_CHUNKS), D>>>(batch);
    k_pool2<<<N_GRAPHS, D>>>(out);
}